// round 16
// baseline (speedup 1.0000x reference)
#include <cuda_runtime.h>
#include <cuda_bf16.h>
#include <math.h>
#include <stdint.h>

#define BATCH 256
#define SEQ   256
#define EMB   512
#define HID   1024
#define G4    4096

typedef __nv_bfloat16 bf16;

// ===========================================================================
// Device global scratch
// ===========================================================================
static __device__ __align__(128) float d_Af[(size_t)SEQ * BATCH * G4];   // preacts fwd (UNpermuted cols)
static __device__ __align__(128) float d_Ab[(size_t)SEQ * BATCH * G4];   // preacts bwd (step-indexed)
static __device__ float d_hbuf[2][2 * BATCH * HID];                      // fp32 h (final only; head reads)
static __device__ float d_cbuf[2 * BATCH * HID];                         // fp32 cell state
static __device__ __align__(128) bf16 d_WxTh[(size_t)2 * G4 * EMB];      // WxT[dir][c][e] hi
static __device__ __align__(128) bf16 d_WxTl[(size_t)2 * G4 * EMB];      // lo
static __device__ __align__(128) bf16 d_WhTh[(size_t)2 * G4 * HID];      // WhT[dir][c][k] hi
static __device__ __align__(128) bf16 d_WhTl[(size_t)2 * G4 * HID];      // lo
static __device__ __align__(128) bf16 d_xh[(size_t)SEQ * BATCH * EMB];   // x hi
static __device__ __align__(128) bf16 d_xl[(size_t)SEQ * BATCH * EMB];   // x lo
static __device__ __align__(128) bf16 d_hh[2][(size_t)2 * BATCH * HID];  // h hi ping-pong (GEMM operand)
static __device__ __align__(128) bf16 d_hl[2][(size_t)2 * BATCH * HID];  // h lo ping-pong

__device__ __forceinline__ float sigmf_(float x) { return 1.0f / (1.0f + expf(-x)); }

// ===========================================================================
// PTX helpers (compute_103-legal: cp.async, ldmatrix, mma.sync)
// ===========================================================================
__device__ __forceinline__ uint32_t smem_u32(const void* p) {
    uint32_t a;
    asm("{ .reg .u64 t; cvta.to.shared.u64 t, %1; cvt.u32.u64 %0, t; }" : "=r"(a) : "l"(p));
    return a;
}
__device__ __forceinline__ void cpa16(uint32_t d, const void* s) {
    asm volatile("cp.async.cg.shared.global [%0], [%1], 16;" :: "r"(d), "l"(s) : "memory");
}
#define CP_COMMIT() asm volatile("cp.async.commit_group;" ::: "memory")
#define CP_WAIT(n)  asm volatile("cp.async.wait_group %0;" :: "n"(n) : "memory")

__device__ __forceinline__ void ldsm4(uint32_t* r, uint32_t addr) {
    asm volatile("ldmatrix.sync.aligned.m8n8.x4.shared.b16 {%0,%1,%2,%3}, [%4];"
        : "=r"(r[0]), "=r"(r[1]), "=r"(r[2]), "=r"(r[3]) : "r"(addr));
}
__device__ __forceinline__ void ldsm2(uint32_t* r, uint32_t addr) {
    asm volatile("ldmatrix.sync.aligned.m8n8.x2.shared.b16 {%0,%1}, [%2];"
        : "=r"(r[0]), "=r"(r[1]) : "r"(addr));
}
__device__ __forceinline__ void mma16816(float* c, const uint32_t* a, const uint32_t* b) {
    asm volatile("mma.sync.aligned.m16n8k16.row.col.f32.bf16.bf16.f32 "
        "{%0,%1,%2,%3}, {%4,%5,%6,%7}, {%8,%9}, {%0,%1,%2,%3};"
        : "+f"(c[0]), "+f"(c[1]), "+f"(c[2]), "+f"(c[3])
        : "r"(a[0]), "r"(a[1]), "r"(a[2]), "r"(a[3]), "r"(b[0]), "r"(b[1]));
}

// ===========================================================================
// Round-12 certified core (pregemm only): 3 stages x 16KB, chunk=16, 32B rows
// ===========================================================================
#define TILE_SZ   4096
#define STAGE_SZ  (4 * TILE_SZ)
#define NSTAGE    3
#define SMEM_TOT  (NSTAGE * STAGE_SZ)   // 48KB static

__device__ __forceinline__ void load_stage(uint32_t st, uint32_t so,
    const bf16* __restrict__ pAh, const bf16* __restrict__ pAl,
    const bf16* __restrict__ pBh, const bf16* __restrict__ pBl, int kc)
{
    cpa16(st + 0 * TILE_SZ + so, pAh + kc);
    cpa16(st + 1 * TILE_SZ + so, pAl + kc);
    cpa16(st + 2 * TILE_SZ + so, pBh + kc);
    cpa16(st + 3 * TILE_SZ + so, pBl + kc);
}

__device__ __forceinline__ void gemm_core(uint32_t sb, int tid,
    const bf16* __restrict__ pAh, const bf16* __restrict__ pAl,
    const bf16* __restrict__ pBh, const bf16* __restrict__ pBl,
    int K, float acc[16][4])
{
    const int lane = tid & 31, wid = tid >> 5;
    const int wm = (wid >> 2) * 64;
    const int wn = (wid & 3) * 32;
    const int r  = lane & 7, g = lane >> 3;
    const int lr = lane & 15, br = lr & 7, bg = lr >> 3;
    const uint32_t so = (uint32_t)(tid >> 1) * 32 + (tid & 1) * 16;

    const int NCH = K / 16;
    load_stage(sb + 0 * STAGE_SZ, so, pAh, pAl, pBh, pBl, 0);
    CP_COMMIT();
    load_stage(sb + 1 * STAGE_SZ, so, pAh, pAl, pBh, pBl, 16);
    CP_COMMIT();

    int stage = 0;
    for (int c = 0; c < NCH; c++) {
        if (c + 2 < NCH) {
            int s2 = stage + 2; if (s2 >= NSTAGE) s2 -= NSTAGE;
            load_stage(sb + s2 * STAGE_SZ, so, pAh, pAl, pBh, pBl, (c + 2) * 16);
            CP_COMMIT();
            CP_WAIT(2);
        } else if (c + 1 < NCH) {
            CP_WAIT(1);
        } else {
            CP_WAIT(0);
        }
        __syncthreads();

        const uint32_t st = sb + stage * STAGE_SZ;
        uint32_t ah[4][4], al[4][4];
#pragma unroll
        for (int fm = 0; fm < 4; fm++) {
            uint32_t byo = (uint32_t)(wm + fm * 16 + r + (g & 1) * 8) * 32 + (g >> 1) * 16;
            ldsm4(ah[fm], st + 0 * TILE_SZ + byo);
            ldsm4(al[fm], st + 1 * TILE_SZ + byo);
        }
        uint32_t bh[4][2], bl[4][2];
#pragma unroll
        for (int fn = 0; fn < 4; fn++) {
            uint32_t byo = (uint32_t)(wn + fn * 8 + br) * 32 + bg * 16;
            ldsm2(bh[fn], st + 2 * TILE_SZ + byo);
            ldsm2(bl[fn], st + 3 * TILE_SZ + byo);
        }
#pragma unroll
        for (int fm = 0; fm < 4; fm++)
#pragma unroll
            for (int fn = 0; fn < 4; fn++) {
                mma16816(acc[fm * 4 + fn], ah[fm], bh[fn]);
                mma16816(acc[fm * 4 + fn], ah[fm], bl[fn]);
                mma16816(acc[fm * 4 + fn], al[fm], bh[fn]);
            }
        __syncthreads();

        if (++stage >= NSTAGE) stage = 0;
    }
}

// ===========================================================================
// Step core: CTA tile 128(M) x 64(N), chunk=64 (128B rows), SW128 swizzle.
// Stage = A hi/lo 16KB each + B hi/lo 8KB each = 48KB; 2 stages = 96KB dynamic
// -> 2 CTAs/SM. Warp tile 64x16 (8 warps 2x4). acc[8][4].
// ===========================================================================
#define ATILE_SZ   16384                 // 128 rows x 128B
#define BTILE_SZ   8192                  // 64 rows x 128B
#define NSTAGE_SZ  (2 * ATILE_SZ + 2 * BTILE_SZ)   // 49152
#define NSMEM_TOT  (2 * NSTAGE_SZ)       // 98304 dynamic
#define OFF_AH     0
#define OFF_AL     ATILE_SZ
#define OFF_BH     (2 * ATILE_SZ)
#define OFF_BL     (2 * ATILE_SZ + BTILE_SZ)

__device__ __forceinline__ uint32_t swz128(uint32_t o) { return o ^ ((o >> 3) & 0x70); }

// A: thread -> row=tid>>1 (128 rows), half=tid&1 (64B each); 4 cpa16 per tile.
// B: thread -> row=tid>>2 (64 rows),  q=tid&3 (32B each);   2 cpa16 per tile.
// Caller pre-offsets pointers to this thread's (row, sub-offset) base.
__device__ __forceinline__ void load_stage_n64(uint32_t st, uint32_t soA, uint32_t soB,
    const bf16* __restrict__ pAh, const bf16* __restrict__ pAl,
    const bf16* __restrict__ pBh, const bf16* __restrict__ pBl, int kc)
{
#pragma unroll
    for (int j = 0; j < 4; j++) {
        uint32_t so = swz128(soA + j * 16);
        cpa16(st + OFF_AH + so, pAh + kc + j * 8);
        cpa16(st + OFF_AL + so, pAl + kc + j * 8);
    }
#pragma unroll
    for (int j = 0; j < 2; j++) {
        uint32_t so = swz128(soB + j * 16);
        cpa16(st + OFF_BH + so, pBh + kc + j * 8);
        cpa16(st + OFF_BL + so, pBl + kc + j * 8);
    }
}

__device__ __forceinline__ void gemm_core_n64(uint32_t sb, int tid,
    const bf16* __restrict__ pAh, const bf16* __restrict__ pAl,
    const bf16* __restrict__ pBh, const bf16* __restrict__ pBl,
    int K, float acc[8][4])
{
    const int lane = tid & 31, wid = tid >> 5;
    const int wm = (wid >> 2) * 64;
    const int wn = (wid & 3) * 16;
    const int r  = lane & 7, g = lane >> 3;
    const int lr = lane & 15, br = lr & 7, bg = lr >> 3;
    const uint32_t soA = (uint32_t)(tid >> 1) * 128 + (tid & 1) * 64;
    const uint32_t soB = (uint32_t)(tid >> 2) * 128 + (tid & 3) * 32;

    const int NCH = K / 64;
    load_stage_n64(sb, soA, soB, pAh, pAl, pBh, pBl, 0);
    CP_COMMIT();

    for (int c = 0; c < NCH; c++) {
        if (c + 1 < NCH) {
            load_stage_n64(sb + ((c + 1) & 1) * NSTAGE_SZ, soA, soB, pAh, pAl, pBh, pBl, (c + 1) * 64);
            CP_COMMIT();
            CP_WAIT(1);
        } else {
            CP_WAIT(0);
        }
        __syncthreads();

        const uint32_t st = sb + (c & 1) * NSTAGE_SZ;
#pragma unroll
        for (int kk = 0; kk < 4; kk++) {
            uint32_t ah[4][4], al[4][4];
#pragma unroll
            for (int fm = 0; fm < 4; fm++) {
                uint32_t byo = swz128((uint32_t)(wm + fm * 16 + r + (g & 1) * 8) * 128
                                      + (kk * 2 + (g >> 1)) * 16);
                ldsm4(ah[fm], st + OFF_AH + byo);
                ldsm4(al[fm], st + OFF_AL + byo);
            }
            uint32_t bh[2][2], bl[2][2];
#pragma unroll
            for (int fn = 0; fn < 2; fn++) {
                uint32_t byo = swz128((uint32_t)(wn + fn * 8 + br) * 128 + (kk * 2 + bg) * 16);
                ldsm2(bh[fn], st + OFF_BH + byo);
                ldsm2(bl[fn], st + OFF_BL + byo);
            }
#pragma unroll
            for (int fm = 0; fm < 4; fm++)
#pragma unroll
                for (int fn = 0; fn < 2; fn++) {
                    mma16816(acc[fm * 2 + fn], ah[fm], bh[fn]);
                    mma16816(acc[fm * 2 + fn], ah[fm], bl[fn]);
                    mma16816(acc[fm * 2 + fn], al[fm], bh[fn]);
                }
        }
        __syncthreads();
    }
}

// ===========================================================================
// Prep kernels — device globals referenced INSIDE kernels only (ATS pitfall:
// passing a __device__ symbol as a host-side kernel arg writes the host shadow).
// ===========================================================================
__global__ void init_state_kernel() {
    int i = blockIdx.x * blockDim.x + threadIdx.x;
    if (i < 2 * BATCH * HID) {
        d_hbuf[0][i] = 0.0f;
        d_cbuf[i]    = 0.0f;
        d_hh[0][i] = __float2bfloat16(0.0f);
        d_hl[0][i] = __float2bfloat16(0.0f);
    }
}

__global__ void split_x_kernel(const int* __restrict__ inputs, const float* __restrict__ emb) {
    size_t idx = (size_t)blockIdx.x * blockDim.x + threadIdx.x;
    if (idx >= (size_t)SEQ * BATCH * EMB) return;
    int e = idx & (EMB - 1);
    size_t rr = idx >> 9;
    int b = rr & (BATCH - 1);
    int t = rr >> 8;
    int v = inputs[b * SEQ + t];
    float f = emb[(size_t)v * EMB + e];
    bf16 hi = __float2bfloat16(f);
    d_xh[idx] = hi;
    d_xl[idx] = __float2bfloat16(f - __bfloat162float(hi));
}

// Plain transpose + split of Wx: d_WxT*[dir][c][e] = Wx[e][c]
__global__ void prep_wx_kernel(const float* __restrict__ Wf, const float* __restrict__ Wb) {
    const int z = blockIdx.z;
    const float* __restrict__ W = z ? Wb : Wf;
    __shared__ float tile[32][33];
    const int k0 = blockIdx.x * 32, c0 = blockIdx.y * 32;
    const int tx = threadIdx.x, ty = threadIdx.y;
#pragma unroll
    for (int i = 0; i < 4; i++)
        tile[ty + 8 * i][tx] = W[(size_t)(k0 + ty + 8 * i) * G4 + c0 + tx];
    __syncthreads();
#pragma unroll
    for (int i = 0; i < 4; i++) {
        int cl = ty + 8 * i;
        int c = c0 + cl;
        float v = tile[tx][cl];
        bf16 hi = __float2bfloat16(v);
        size_t o = ((size_t)z * G4 + c) * EMB + k0 + tx;
        d_WxTh[o] = hi;
        d_WxTl[o] = __float2bfloat16(v - __bfloat162float(hi));
    }
}

// Plain transpose + split of Wh: d_WhT*[dir][c][k] = Wh[k][c]
__global__ void prep_wh_kernel(const float* __restrict__ Wf, const float* __restrict__ Wb) {
    const int z = blockIdx.z;
    const float* __restrict__ W = z ? Wb : Wf;
    __shared__ float tile[32][33];
    const int k0 = blockIdx.x * 32, c0 = blockIdx.y * 32;
    const int tx = threadIdx.x, ty = threadIdx.y;
#pragma unroll
    for (int i = 0; i < 4; i++)
        tile[ty + 8 * i][tx] = W[(size_t)(k0 + ty + 8 * i) * G4 + c0 + tx];
    __syncthreads();
#pragma unroll
    for (int i = 0; i < 4; i++) {
        int cl = ty + 8 * i;
        int c = c0 + cl;
        float v = tile[tx][cl];
        bf16 hi = __float2bfloat16(v);
        size_t o = ((size_t)z * G4 + c) * HID + k0 + tx;
        d_WhTh[o] = hi;
        d_WhTl[o] = __float2bfloat16(v - __bfloat162float(hi));
    }
}

// ===========================================================================
// HMMA pre-GEMM (round-12 certified, unchanged): grid (32, 512, 2), 256 thr
// ===========================================================================
__global__ __launch_bounds__(256, 2) void tc_pregemm_kernel(
    const float* __restrict__ bfp, const float* __restrict__ bbp)
{
    static __shared__ char smem[SMEM_TOT];
    const int tid = threadIdx.x;
    const int n0 = blockIdx.x * 128;
    const int m0 = blockIdx.y * 128;
    const int dir = blockIdx.z;
    uint32_t sb = smem_u32(smem);

    const int t = m0 >> 8, b0 = m0 & 255;
    const int tsrc = dir ? (SEQ - 1 - t) : t;
    const int row = tid >> 1, half = tid & 1;
    const size_t xoff = ((size_t)tsrc * BATCH + b0 + row) * EMB + half * 8;
    const size_t woff = ((size_t)dir * G4 + n0 + row) * EMB + half * 8;

    float acc[16][4];
#pragma unroll
    for (int i = 0; i < 16; i++)
#pragma unroll
        for (int j = 0; j < 4; j++) acc[i][j] = 0.0f;

    gemm_core(sb, tid, d_xh + xoff, d_xl + xoff, d_WxTh + woff, d_WxTl + woff, EMB, acc);

    const int lane = tid & 31, wid = tid >> 5;
    const int wm = (wid >> 2) * 64, wn = (wid & 3) * 32;
    const int mr = lane >> 2, nc = (lane & 3) * 2;
    float* Aout = dir ? d_Ab : d_Af;
    const float* bp = dir ? bbp : bfp;
#pragma unroll
    for (int fn = 0; fn < 4; fn++) {
        const int n = n0 + wn + fn * 8 + nc;
        const float2 b2 = *(const float2*)(bp + n);
#pragma unroll
        for (int fm = 0; fm < 4; fm++) {
            const float* a = acc[fm * 4 + fn];
            const int m = m0 + wm + fm * 16 + mr;
            *(float2*)(Aout + (size_t)m * G4 + n)       = make_float2(a[0] + b2.x, a[1] + b2.y);
            *(float2*)(Aout + (size_t)(m + 8) * G4 + n) = make_float2(a[2] + b2.x, a[3] + b2.y);
        }
    }
}

// ===========================================================================
// HMMA recurrent step (N=64 tile, 96KB dynamic smem, 2 CTAs/SM):
// D = h_prev @ WhT (4 gate slices of 16 jh per CTA); gates = D + A[t];
// update c, h. grid (HID/16=64, BATCH/128=2, 2) = 256 CTAs, 256 threads
// ===========================================================================
__global__ __launch_bounds__(256, 2) void tc_step_kernel(int t) {
    extern __shared__ char dsm[];
    const int tid = threadIdx.x;
    const int jh0 = blockIdx.x * 16;
    const int b0  = blockIdx.y * 128;
    const int dir = blockIdx.z;
    uint32_t sb = smem_u32(dsm);

    // A operand: h_prev rows b0+rowA. B operand rows (0..63):
    //   WhT row = dir*G4 + (n>>4)*HID + jh0 + (n&15)
    const int rowA = tid >> 1;
    const size_t hoff = ((size_t)dir * BATCH + b0 + rowA) * HID + (tid & 1) * 32;
    const int rowB = tid >> 2;
    const size_t woff = ((size_t)dir * G4 + (size_t)(rowB >> 4) * HID + jh0 + (rowB & 15)) * HID
                      + (tid & 3) * 16;

    float acc[8][4];
#pragma unroll
    for (int i = 0; i < 8; i++)
#pragma unroll
        for (int j = 0; j < 4; j++) acc[i][j] = 0.0f;

    gemm_core_n64(sb, tid, d_hh[t & 1] + hoff, d_hl[t & 1] + hoff,
                  d_WhTh + woff, d_WhTl + woff, HID, acc);

    // Single-pass epilogue: C = 128x64 fp32 (32KB) in stage-0 smem region.
    float* Cs = (float*)dsm;
    const int lane = tid & 31, wid = tid >> 5;
    const int wm = (wid >> 2) * 64;
    const int wn = (wid & 3) * 16;
    const int mr = lane >> 2, nc = (lane & 3) * 2;

    // core ended with __syncthreads(); stage-0 region free to overwrite
#pragma unroll
    for (int fm = 0; fm < 4; fm++)
#pragma unroll
        for (int fn = 0; fn < 2; fn++) {
            const float* a = acc[fm * 2 + fn];
            const int lm = wm + fm * 16 + mr;
            const int n = wn + fn * 8 + nc;
            *(float2*)&Cs[lm * 64 + n]       = make_float2(a[0], a[1]);
            *(float2*)&Cs[(lm + 8) * 64 + n] = make_float2(a[2], a[3]);
        }
    __syncthreads();

    // Consumer: thread -> (r = tid>>1 of 128 rows, half = tid&1 -> 8 jh of 16)
    {
        const int r = tid >> 1, half = tid & 1;
        const int b = b0 + r;
        const int jj0 = half * 8;
        const float* Crow = Cs + r * 64 + jj0;
        const float* Arow = (dir ? d_Ab : d_Af) + ((size_t)t * BATCH + b) * G4 + jh0 + jj0;
        const size_t sidx = ((size_t)dir * BATCH + b) * HID + jh0 + jj0;
        float* cp = d_cbuf + sidx;
        bf16* hhp = d_hh[(t + 1) & 1] + sidx;
        bf16* hlp = d_hl[(t + 1) & 1] + sidx;

        float gv[4][8];
#pragma unroll
        for (int g = 0; g < 4; g++) {
            float4 x0 = *(const float4*)(Crow + g * 16);
            float4 x1 = *(const float4*)(Crow + g * 16 + 4);
            float4 y0 = *(const float4*)(Arow + (size_t)g * HID);
            float4 y1 = *(const float4*)(Arow + (size_t)g * HID + 4);
            gv[g][0] = x0.x + y0.x; gv[g][1] = x0.y + y0.y;
            gv[g][2] = x0.z + y0.z; gv[g][3] = x0.w + y0.w;
            gv[g][4] = x1.x + y1.x; gv[g][5] = x1.y + y1.y;
            gv[g][6] = x1.z + y1.z; gv[g][7] = x1.w + y1.w;
        }
        float cold[8];
        *(float4*)(cold)     = *(const float4*)(cp);
        *(float4*)(cold + 4) = *(const float4*)(cp + 4);

        float cnew[8], hnew[8];
        bf16 outh[8], outl[8];
#pragma unroll
        for (int q = 0; q < 8; q++) {
            float cn = sigmf_(gv[1][q]) * cold[q] + sigmf_(gv[0][q]) * tanhf(gv[3][q]);
            float hn = sigmf_(gv[2][q]) * tanhf(cn);
            cnew[q] = cn;
            hnew[q] = hn;
            bf16 hi = __float2bfloat16(hn);
            outh[q] = hi;
            outl[q] = __float2bfloat16(hn - __bfloat162float(hi));
        }
        *(float4*)(cp)      = *(float4*)(cnew);
        *(float4*)(cp + 4)  = *(float4*)(cnew + 4);
        *(int4*)hhp = *(int4*)outh;
        *(int4*)hlp = *(int4*)outl;
        if (t == SEQ - 1) {   // head only needs the final fp32 h
            float* hfp = d_hbuf[(t + 1) & 1] + sidx;
            *(float4*)(hfp)     = *(float4*)(hnew);
            *(float4*)(hfp + 4) = *(float4*)(hnew + 4);
        }
    }
}

// ===========================================================================
// Head (proven; reads fp32 h)
// ===========================================================================
__global__ __launch_bounds__(256) void head_kernel(
    const float* __restrict__ Whq, const float* __restrict__ bq, float* __restrict__ out)
{
    const int b   = blockIdx.x;
    const int tid = threadIdx.x;
    const float* hf = d_hbuf[0] + 0 * BATCH * HID + (size_t)b * HID;
    const float* hb = d_hbuf[0] + 1 * BATCH * HID + (size_t)b * HID;

    float p[10];
#pragma unroll
    for (int q = 0; q < 10; q++) p[q] = 0.0f;

    for (int k = tid; k < HID; k += 256) {
        float s = hf[k] + hb[k];
        const float* w = Whq + k * 10;
#pragma unroll
        for (int q = 0; q < 10; q++) p[q] += s * w[q];
    }

    __shared__ float red[256 * 10];
#pragma unroll
    for (int q = 0; q < 10; q++) red[tid * 10 + q] = p[q];
    __syncthreads();

    __shared__ float tot[10];
    if (tid < 10) {
        float s = 0.0f;
        for (int i = 0; i < 256; i++) s += red[i * 10 + tid];
        tot[tid] = s + bq[tid];
    }
    __syncthreads();

    if (tid == 0) {
        float m = tot[0];
        for (int q = 1; q < 10; q++) m = fmaxf(m, tot[q]);
        float e[10], se = 0.0f;
        for (int q = 0; q < 10; q++) { e[q] = expf(tot[q] - m); se += e[q]; }
        float inv = 1.0f / se;
        for (int q = 0; q < 10; q++) out[b * 10 + q] = e[q] * inv;
    }
}

// ===========================================================================
// Launch
// ===========================================================================
extern "C" void kernel_launch(void* const* d_in, const int* in_sizes, int n_in,
                              void* d_out, int out_size)
{
    const int*   inputs = (const int*)  d_in[0];
    const float* emb    = (const float*)d_in[1];
    const float* Wx_f   = (const float*)d_in[2];
    const float* Wh_f   = (const float*)d_in[3];
    const float* b_f    = (const float*)d_in[4];
    const float* Wx_b   = (const float*)d_in[5];
    const float* Wh_b   = (const float*)d_in[6];
    const float* b_b    = (const float*)d_in[7];
    const float* W_hq   = (const float*)d_in[8];
    const float* b_q    = (const float*)d_in[9];
    float* out = (float*)d_out;

    cudaFuncSetAttribute(tc_step_kernel, cudaFuncAttributeMaxDynamicSharedMemorySize, NSMEM_TOT);

    init_state_kernel<<<(2 * BATCH * HID + 255) / 256, 256>>>();
    split_x_kernel<<<(int)(((size_t)SEQ * BATCH * EMB + 255) / 256), 256>>>(inputs, emb);
    prep_wx_kernel<<<dim3(EMB / 32, G4 / 32, 2), dim3(32, 8)>>>(Wx_f, Wx_b);
    prep_wh_kernel<<<dim3(HID / 32, G4 / 32, 2), dim3(32, 8)>>>(Wh_f, Wh_b);

    tc_pregemm_kernel<<<dim3(G4 / 128, SEQ * BATCH / 128, 2), 256>>>(b_f, b_b);

    for (int t = 0; t < SEQ; t++)
        tc_step_kernel<<<dim3(HID / 16, BATCH / 128, 2), 256, NSMEM_TOT>>>(t);

    head_kernel<<<BATCH, 256>>>(W_hq, b_q, out);
    (void)in_sizes; (void)n_in; (void)out_size;
}

// round 17
// speedup vs baseline: 1.2133x; 1.2133x over previous
#include <cuda_runtime.h>
#include <cuda_bf16.h>
#include <cuda_fp16.h>
#include <math.h>
#include <stdint.h>

#define BATCH 256
#define SEQ   256
#define EMB   512
#define HID   1024
#define G4    4096

typedef __nv_bfloat16 bf16;

// ===========================================================================
// Device global scratch
// ===========================================================================
static __device__ __align__(128) float d_Af[(size_t)SEQ * BATCH * G4];   // preacts fwd (UNpermuted cols)
static __device__ __align__(128) float d_Ab[(size_t)SEQ * BATCH * G4];   // preacts bwd (step-indexed)
static __device__ float d_hbuf[2][2 * BATCH * HID];                      // fp32 h (final only; head reads)
static __device__ float d_cbuf[2 * BATCH * HID];                         // fp32 cell state
static __device__ __align__(128) bf16 d_WxTh[(size_t)2 * G4 * EMB];      // WxT[dir][c][e] hi (bf16, pregemm)
static __device__ __align__(128) bf16 d_WxTl[(size_t)2 * G4 * EMB];      // lo
static __device__ __align__(128) __half d_Whf16[(size_t)2 * G4 * HID];   // WhT[dir][c][k] single fp16 (step)
static __device__ __align__(128) bf16 d_xh[(size_t)SEQ * BATCH * EMB];   // x hi
static __device__ __align__(128) bf16 d_xl[(size_t)SEQ * BATCH * EMB];   // x lo
static __device__ __align__(128) __half d_hh[2][(size_t)2 * BATCH * HID]; // h hi ping-pong (fp16)
static __device__ __align__(128) __half d_hl[2][(size_t)2 * BATCH * HID]; // h lo ping-pong (fp16)

__device__ __forceinline__ float sigmf_(float x) { return 1.0f / (1.0f + expf(-x)); }

// ===========================================================================
// PTX helpers (compute_103-legal: cp.async, ldmatrix, mma.sync)
// ===========================================================================
__device__ __forceinline__ uint32_t smem_u32(const void* p) {
    uint32_t a;
    asm("{ .reg .u64 t; cvta.to.shared.u64 t, %1; cvt.u32.u64 %0, t; }" : "=r"(a) : "l"(p));
    return a;
}
__device__ __forceinline__ void cpa16(uint32_t d, const void* s) {
    asm volatile("cp.async.cg.shared.global [%0], [%1], 16;" :: "r"(d), "l"(s) : "memory");
}
#define CP_COMMIT() asm volatile("cp.async.commit_group;" ::: "memory")
#define CP_WAIT(n)  asm volatile("cp.async.wait_group %0;" :: "n"(n) : "memory")

__device__ __forceinline__ void ldsm4(uint32_t* r, uint32_t addr) {
    asm volatile("ldmatrix.sync.aligned.m8n8.x4.shared.b16 {%0,%1,%2,%3}, [%4];"
        : "=r"(r[0]), "=r"(r[1]), "=r"(r[2]), "=r"(r[3]) : "r"(addr));
}
__device__ __forceinline__ void ldsm2(uint32_t* r, uint32_t addr) {
    asm volatile("ldmatrix.sync.aligned.m8n8.x2.shared.b16 {%0,%1}, [%2];"
        : "=r"(r[0]), "=r"(r[1]) : "r"(addr));
}
// bf16 MMA (pregemm path)
__device__ __forceinline__ void mma16816(float* c, const uint32_t* a, const uint32_t* b) {
    asm volatile("mma.sync.aligned.m16n8k16.row.col.f32.bf16.bf16.f32 "
        "{%0,%1,%2,%3}, {%4,%5,%6,%7}, {%8,%9}, {%0,%1,%2,%3};"
        : "+f"(c[0]), "+f"(c[1]), "+f"(c[2]), "+f"(c[3])
        : "r"(a[0]), "r"(a[1]), "r"(a[2]), "r"(a[3]), "r"(b[0]), "r"(b[1]));
}
// fp16 MMA (step path)
__device__ __forceinline__ void mma16816h(float* c, const uint32_t* a, const uint32_t* b) {
    asm volatile("mma.sync.aligned.m16n8k16.row.col.f32.f16.f16.f32 "
        "{%0,%1,%2,%3}, {%4,%5,%6,%7}, {%8,%9}, {%0,%1,%2,%3};"
        : "+f"(c[0]), "+f"(c[1]), "+f"(c[2]), "+f"(c[3])
        : "r"(a[0]), "r"(a[1]), "r"(a[2]), "r"(a[3]), "r"(b[0]), "r"(b[1]));
}

// ===========================================================================
// Round-12 certified core (pregemm only): 3 stages x 16KB, chunk=16, 32B rows
// ===========================================================================
#define TILE_SZ   4096
#define STAGE_SZ  (4 * TILE_SZ)
#define NSTAGE    3
#define SMEM_TOT  (NSTAGE * STAGE_SZ)   // 48KB static

__device__ __forceinline__ void load_stage(uint32_t st, uint32_t so,
    const bf16* __restrict__ pAh, const bf16* __restrict__ pAl,
    const bf16* __restrict__ pBh, const bf16* __restrict__ pBl, int kc)
{
    cpa16(st + 0 * TILE_SZ + so, pAh + kc);
    cpa16(st + 1 * TILE_SZ + so, pAl + kc);
    cpa16(st + 2 * TILE_SZ + so, pBh + kc);
    cpa16(st + 3 * TILE_SZ + so, pBl + kc);
}

__device__ __forceinline__ void gemm_core(uint32_t sb, int tid,
    const bf16* __restrict__ pAh, const bf16* __restrict__ pAl,
    const bf16* __restrict__ pBh, const bf16* __restrict__ pBl,
    int K, float acc[16][4])
{
    const int lane = tid & 31, wid = tid >> 5;
    const int wm = (wid >> 2) * 64;
    const int wn = (wid & 3) * 32;
    const int r  = lane & 7, g = lane >> 3;
    const int lr = lane & 15, br = lr & 7, bg = lr >> 3;
    const uint32_t so = (uint32_t)(tid >> 1) * 32 + (tid & 1) * 16;

    const int NCH = K / 16;
    load_stage(sb + 0 * STAGE_SZ, so, pAh, pAl, pBh, pBl, 0);
    CP_COMMIT();
    load_stage(sb + 1 * STAGE_SZ, so, pAh, pAl, pBh, pBl, 16);
    CP_COMMIT();

    int stage = 0;
    for (int c = 0; c < NCH; c++) {
        if (c + 2 < NCH) {
            int s2 = stage + 2; if (s2 >= NSTAGE) s2 -= NSTAGE;
            load_stage(sb + s2 * STAGE_SZ, so, pAh, pAl, pBh, pBl, (c + 2) * 16);
            CP_COMMIT();
            CP_WAIT(2);
        } else if (c + 1 < NCH) {
            CP_WAIT(1);
        } else {
            CP_WAIT(0);
        }
        __syncthreads();

        const uint32_t st = sb + stage * STAGE_SZ;
        uint32_t ah[4][4], al[4][4];
#pragma unroll
        for (int fm = 0; fm < 4; fm++) {
            uint32_t byo = (uint32_t)(wm + fm * 16 + r + (g & 1) * 8) * 32 + (g >> 1) * 16;
            ldsm4(ah[fm], st + 0 * TILE_SZ + byo);
            ldsm4(al[fm], st + 1 * TILE_SZ + byo);
        }
        uint32_t bh[4][2], bl[4][2];
#pragma unroll
        for (int fn = 0; fn < 4; fn++) {
            uint32_t byo = (uint32_t)(wn + fn * 8 + br) * 32 + bg * 16;
            ldsm2(bh[fn], st + 2 * TILE_SZ + byo);
            ldsm2(bl[fn], st + 3 * TILE_SZ + byo);
        }
#pragma unroll
        for (int fm = 0; fm < 4; fm++)
#pragma unroll
            for (int fn = 0; fn < 4; fn++) {
                mma16816(acc[fm * 4 + fn], ah[fm], bh[fn]);
                mma16816(acc[fm * 4 + fn], ah[fm], bl[fn]);
                mma16816(acc[fm * 4 + fn], al[fm], bh[fn]);
            }
        __syncthreads();

        if (++stage >= NSTAGE) stage = 0;
    }
}

// ===========================================================================
// Step core (fp16 2-term): CTA tile 128x128, chunk=64 (128B rows), SW128.
// Stage = A-hi 16KB | A-lo 16KB | B 16KB = 48KB; 2 stages = 96KB dynamic.
// D = h_hi @ W + h_lo @ W   (W single fp16; h split fp16 hi/lo)
// ===========================================================================
#define FTILE_SZ   16384                 // 128 rows x 128B
#define FSTAGE_SZ  (3 * FTILE_SZ)        // 49152
#define FSMEM_TOT  (2 * FSTAGE_SZ)       // 98304 dynamic
#define OFF_FAH    0
#define OFF_FAL    FTILE_SZ
#define OFF_FB     (2 * FTILE_SZ)

__device__ __forceinline__ uint32_t swz128(uint32_t o) { return o ^ ((o >> 3) & 0x70); }

// thread -> row = tid>>1, half = tid&1 (64B each); caller pre-offsets pointers.
__device__ __forceinline__ void load_stage_f16(uint32_t st, uint32_t so0,
    const __half* __restrict__ pAh, const __half* __restrict__ pAl,
    const __half* __restrict__ pB, int kc)
{
#pragma unroll
    for (int j = 0; j < 4; j++) {
        uint32_t so = swz128(so0 + j * 16);
        cpa16(st + OFF_FAH + so, pAh + kc + j * 8);
        cpa16(st + OFF_FAL + so, pAl + kc + j * 8);
        cpa16(st + OFF_FB  + so, pB  + kc + j * 8);
    }
}

__device__ __forceinline__ void gemm_core_f16(uint32_t sb, int tid,
    const __half* __restrict__ pAh, const __half* __restrict__ pAl,
    const __half* __restrict__ pB,
    int K, float acc[16][4])
{
    const int lane = tid & 31, wid = tid >> 5;
    const int wm = (wid >> 2) * 64;
    const int wn = (wid & 3) * 32;
    const int r  = lane & 7, g = lane >> 3;
    const int lr = lane & 15, br = lr & 7, bg = lr >> 3;
    const uint32_t so0 = (uint32_t)(tid >> 1) * 128 + (tid & 1) * 64;

    const int NCH = K / 64;
    load_stage_f16(sb, so0, pAh, pAl, pB, 0);
    CP_COMMIT();

    for (int c = 0; c < NCH; c++) {
        if (c + 1 < NCH) {
            load_stage_f16(sb + ((c + 1) & 1) * FSTAGE_SZ, so0, pAh, pAl, pB, (c + 1) * 64);
            CP_COMMIT();
            CP_WAIT(1);
        } else {
            CP_WAIT(0);
        }
        __syncthreads();

        const uint32_t st = sb + (c & 1) * FSTAGE_SZ;
#pragma unroll
        for (int kk = 0; kk < 4; kk++) {
            uint32_t ah[4][4], al[4][4];
#pragma unroll
            for (int fm = 0; fm < 4; fm++) {
                uint32_t byo = swz128((uint32_t)(wm + fm * 16 + r + (g & 1) * 8) * 128
                                      + (kk * 2 + (g >> 1)) * 16);
                ldsm4(ah[fm], st + OFF_FAH + byo);
                ldsm4(al[fm], st + OFF_FAL + byo);
            }
            uint32_t bb[4][2];
#pragma unroll
            for (int fn = 0; fn < 4; fn++) {
                uint32_t byo = swz128((uint32_t)(wn + fn * 8 + br) * 128 + (kk * 2 + bg) * 16);
                ldsm2(bb[fn], st + OFF_FB + byo);
            }
#pragma unroll
            for (int fm = 0; fm < 4; fm++)
#pragma unroll
                for (int fn = 0; fn < 4; fn++) {
                    mma16816h(acc[fm * 4 + fn], ah[fm], bb[fn]);
                    mma16816h(acc[fm * 4 + fn], al[fm], bb[fn]);
                }
        }
        __syncthreads();
    }
}

// ===========================================================================
// Prep kernels — device globals referenced INSIDE kernels only (ATS pitfall:
// passing a __device__ symbol as a host-side kernel arg writes the host shadow).
// ===========================================================================
__global__ void init_state_kernel() {
    int i = blockIdx.x * blockDim.x + threadIdx.x;
    if (i < 2 * BATCH * HID) {
        d_hbuf[0][i] = 0.0f;
        d_cbuf[i]    = 0.0f;
        d_hh[0][i] = __float2half(0.0f);
        d_hl[0][i] = __float2half(0.0f);
    }
}

__global__ void split_x_kernel(const int* __restrict__ inputs, const float* __restrict__ emb) {
    size_t idx = (size_t)blockIdx.x * blockDim.x + threadIdx.x;
    if (idx >= (size_t)SEQ * BATCH * EMB) return;
    int e = idx & (EMB - 1);
    size_t rr = idx >> 9;
    int b = rr & (BATCH - 1);
    int t = rr >> 8;
    int v = inputs[b * SEQ + t];
    float f = emb[(size_t)v * EMB + e];
    bf16 hi = __float2bfloat16(f);
    d_xh[idx] = hi;
    d_xl[idx] = __float2bfloat16(f - __bfloat162float(hi));
}

// Plain transpose + split of Wx: d_WxT*[dir][c][e] = Wx[e][c]  (bf16 hi/lo)
__global__ void prep_wx_kernel(const float* __restrict__ Wf, const float* __restrict__ Wb) {
    const int z = blockIdx.z;
    const float* __restrict__ W = z ? Wb : Wf;
    __shared__ float tile[32][33];
    const int k0 = blockIdx.x * 32, c0 = blockIdx.y * 32;
    const int tx = threadIdx.x, ty = threadIdx.y;
#pragma unroll
    for (int i = 0; i < 4; i++)
        tile[ty + 8 * i][tx] = W[(size_t)(k0 + ty + 8 * i) * G4 + c0 + tx];
    __syncthreads();
#pragma unroll
    for (int i = 0; i < 4; i++) {
        int cl = ty + 8 * i;
        int c = c0 + cl;
        float v = tile[tx][cl];
        bf16 hi = __float2bfloat16(v);
        size_t o = ((size_t)z * G4 + c) * EMB + k0 + tx;
        d_WxTh[o] = hi;
        d_WxTl[o] = __float2bfloat16(v - __bfloat162float(hi));
    }
}

// Plain transpose of Wh to single fp16: d_Whf16[dir][c][k] = (half)Wh[k][c]
__global__ void prep_wh_kernel(const float* __restrict__ Wf, const float* __restrict__ Wb) {
    const int z = blockIdx.z;
    const float* __restrict__ W = z ? Wb : Wf;
    __shared__ float tile[32][33];
    const int k0 = blockIdx.x * 32, c0 = blockIdx.y * 32;
    const int tx = threadIdx.x, ty = threadIdx.y;
#pragma unroll
    for (int i = 0; i < 4; i++)
        tile[ty + 8 * i][tx] = W[(size_t)(k0 + ty + 8 * i) * G4 + c0 + tx];
    __syncthreads();
#pragma unroll
    for (int i = 0; i < 4; i++) {
        int cl = ty + 8 * i;
        int c = c0 + cl;
        float v = tile[tx][cl];
        size_t o = ((size_t)z * G4 + c) * HID + k0 + tx;
        d_Whf16[o] = __float2half_rn(v);
    }
}

// ===========================================================================
// HMMA pre-GEMM (round-12 certified, unchanged): grid (32, 512, 2), 256 thr
// ===========================================================================
__global__ __launch_bounds__(256, 2) void tc_pregemm_kernel(
    const float* __restrict__ bfp, const float* __restrict__ bbp)
{
    static __shared__ char smem[SMEM_TOT];
    const int tid = threadIdx.x;
    const int n0 = blockIdx.x * 128;
    const int m0 = blockIdx.y * 128;
    const int dir = blockIdx.z;
    uint32_t sb = smem_u32(smem);

    const int t = m0 >> 8, b0 = m0 & 255;
    const int tsrc = dir ? (SEQ - 1 - t) : t;
    const int row = tid >> 1, half = tid & 1;
    const size_t xoff = ((size_t)tsrc * BATCH + b0 + row) * EMB + half * 8;
    const size_t woff = ((size_t)dir * G4 + n0 + row) * EMB + half * 8;

    float acc[16][4];
#pragma unroll
    for (int i = 0; i < 16; i++)
#pragma unroll
        for (int j = 0; j < 4; j++) acc[i][j] = 0.0f;

    gemm_core(sb, tid, d_xh + xoff, d_xl + xoff, d_WxTh + woff, d_WxTl + woff, EMB, acc);

    const int lane = tid & 31, wid = tid >> 5;
    const int wm = (wid >> 2) * 64, wn = (wid & 3) * 32;
    const int mr = lane >> 2, nc = (lane & 3) * 2;
    float* Aout = dir ? d_Ab : d_Af;
    const float* bp = dir ? bbp : bfp;
#pragma unroll
    for (int fn = 0; fn < 4; fn++) {
        const int n = n0 + wn + fn * 8 + nc;
        const float2 b2 = *(const float2*)(bp + n);
#pragma unroll
        for (int fm = 0; fm < 4; fm++) {
            const float* a = acc[fm * 4 + fn];
            const int m = m0 + wm + fm * 16 + mr;
            *(float2*)(Aout + (size_t)m * G4 + n)       = make_float2(a[0] + b2.x, a[1] + b2.y);
            *(float2*)(Aout + (size_t)(m + 8) * G4 + n) = make_float2(a[2] + b2.x, a[3] + b2.y);
        }
    }
}

// ===========================================================================
// HMMA recurrent step (fp16 2-term, 96KB dynamic smem):
// D = h_prev @ WhT (4 gate slices of 32 jh per CTA); gates = D + A[t];
// update c, h. grid (HID/32=32, BATCH/128=2, 2) = 128 CTAs, 256 threads
// ===========================================================================
__global__ __launch_bounds__(256, 1) void tc_step_kernel(int t) {
    extern __shared__ char dsm[];
    const int tid = threadIdx.x;
    const int jh0 = blockIdx.x * 32;
    const int b0  = blockIdx.y * 128;
    const int dir = blockIdx.z;
    uint32_t sb = smem_u32(dsm);

    // A operand: h_prev rows b0+row; B operand: WhT row (g*HID + jh0 + jl), g=row>>5
    const int row = tid >> 1;
    const int j0e = (tid & 1) * 32;   // element offset of this thread's 4x16B slot
    const size_t hoff = ((size_t)dir * BATCH + b0 + row) * HID + j0e;
    const size_t woff = ((size_t)dir * G4 + (size_t)(row >> 5) * HID + jh0 + (row & 31)) * HID + j0e;

    float acc[16][4];
#pragma unroll
    for (int i = 0; i < 16; i++)
#pragma unroll
        for (int j = 0; j < 4; j++) acc[i][j] = 0.0f;

    gemm_core_f16(sb, tid, d_hh[t & 1] + hoff, d_hl[t & 1] + hoff,
                  d_Whf16 + woff, HID, acc);

    // Two-pass epilogue through 64x128 fp32 C half-tile (32KB, reuses stage smem)
    float* Cs = (float*)dsm;
    const int lane = tid & 31, wid = tid >> 5;
    const int wgrp = wid >> 2;
    const int wn = (wid & 3) * 32;
    const int mr = lane >> 2, nc = (lane & 3) * 2;

#pragma unroll
    for (int hh = 0; hh < 2; hh++) {
        __syncthreads();
        if (wgrp == hh) {
#pragma unroll
            for (int fm = 0; fm < 4; fm++)
#pragma unroll
                for (int fn = 0; fn < 4; fn++) {
                    const float* a = acc[fm * 4 + fn];
                    const int lm = fm * 16 + mr;
                    const int n = wn + fn * 8 + nc;
                    *(float2*)&Cs[lm * 128 + n]       = make_float2(a[0], a[1]);
                    *(float2*)&Cs[(lm + 8) * 128 + n] = make_float2(a[2], a[3]);
                }
        }
        __syncthreads();

        // Consumer: thread -> (r = tid>>2 of 64 rows, 8 jl values)
        const int r = tid >> 2, qq = tid & 3;
        const int b = b0 + hh * 64 + r;
        const int jl0 = qq * 8;
        const float* Arow = (dir ? d_Ab : d_Af) + ((size_t)t * BATCH + b) * G4 + jh0 + jl0;
        const float* Crow = Cs + r * 128 + jl0;
        const size_t sidx = ((size_t)dir * BATCH + b) * HID + jh0 + jl0;
        float* cp = d_cbuf + sidx;
        __half* hhp = d_hh[(t + 1) & 1] + sidx;
        __half* hlp = d_hl[(t + 1) & 1] + sidx;

        float gv[4][8];
#pragma unroll
        for (int g = 0; g < 4; g++) {
            float4 x0 = *(const float4*)(Crow + g * 32);
            float4 x1 = *(const float4*)(Crow + g * 32 + 4);
            float4 y0 = *(const float4*)(Arow + (size_t)g * HID);
            float4 y1 = *(const float4*)(Arow + (size_t)g * HID + 4);
            gv[g][0] = x0.x + y0.x; gv[g][1] = x0.y + y0.y;
            gv[g][2] = x0.z + y0.z; gv[g][3] = x0.w + y0.w;
            gv[g][4] = x1.x + y1.x; gv[g][5] = x1.y + y1.y;
            gv[g][6] = x1.z + y1.z; gv[g][7] = x1.w + y1.w;
        }
        float cold[8];
        *(float4*)(cold)     = *(const float4*)(cp);
        *(float4*)(cold + 4) = *(const float4*)(cp + 4);

        float cnew[8], hnew[8];
        __half outh[8], outl[8];
#pragma unroll
        for (int q = 0; q < 8; q++) {
            float cn = sigmf_(gv[1][q]) * cold[q] + sigmf_(gv[0][q]) * tanhf(gv[3][q]);
            float hn = sigmf_(gv[2][q]) * tanhf(cn);
            cnew[q] = cn;
            hnew[q] = hn;
            __half hi = __float2half_rn(hn);
            outh[q] = hi;
            outl[q] = __float2half_rn(hn - __half2float(hi));
        }
        *(float4*)(cp)      = *(float4*)(cnew);
        *(float4*)(cp + 4)  = *(float4*)(cnew + 4);
        *(int4*)hhp = *(int4*)outh;
        *(int4*)hlp = *(int4*)outl;
        if (t == SEQ - 1) {   // head only needs the final fp32 h
            float* hfp = d_hbuf[(t + 1) & 1] + sidx;
            *(float4*)(hfp)     = *(float4*)(hnew);
            *(float4*)(hfp + 4) = *(float4*)(hnew + 4);
        }
    }
}

// ===========================================================================
// Head (proven; reads fp32 h)
// ===========================================================================
__global__ __launch_bounds__(256) void head_kernel(
    const float* __restrict__ Whq, const float* __restrict__ bq, float* __restrict__ out)
{
    const int b   = blockIdx.x;
    const int tid = threadIdx.x;
    const float* hf = d_hbuf[0] + 0 * BATCH * HID + (size_t)b * HID;
    const float* hb = d_hbuf[0] + 1 * BATCH * HID + (size_t)b * HID;

    float p[10];
#pragma unroll
    for (int q = 0; q < 10; q++) p[q] = 0.0f;

    for (int k = tid; k < HID; k += 256) {
        float s = hf[k] + hb[k];
        const float* w = Whq + k * 10;
#pragma unroll
        for (int q = 0; q < 10; q++) p[q] += s * w[q];
    }

    __shared__ float red[256 * 10];
#pragma unroll
    for (int q = 0; q < 10; q++) red[tid * 10 + q] = p[q];
    __syncthreads();

    __shared__ float tot[10];
    if (tid < 10) {
        float s = 0.0f;
        for (int i = 0; i < 256; i++) s += red[i * 10 + tid];
        tot[tid] = s + bq[tid];
    }
    __syncthreads();

    if (tid == 0) {
        float m = tot[0];
        for (int q = 1; q < 10; q++) m = fmaxf(m, tot[q]);
        float e[10], se = 0.0f;
        for (int q = 0; q < 10; q++) { e[q] = expf(tot[q] - m); se += e[q]; }
        float inv = 1.0f / se;
        for (int q = 0; q < 10; q++) out[b * 10 + q] = e[q] * inv;
    }
}

// ===========================================================================
// Launch
// ===========================================================================
extern "C" void kernel_launch(void* const* d_in, const int* in_sizes, int n_in,
                              void* d_out, int out_size)
{
    const int*   inputs = (const int*)  d_in[0];
    const float* emb    = (const float*)d_in[1];
    const float* Wx_f   = (const float*)d_in[2];
    const float* Wh_f   = (const float*)d_in[3];
    const float* b_f    = (const float*)d_in[4];
    const float* Wx_b   = (const float*)d_in[5];
    const float* Wh_b   = (const float*)d_in[6];
    const float* b_b    = (const float*)d_in[7];
    const float* W_hq   = (const float*)d_in[8];
    const float* b_q    = (const float*)d_in[9];
    float* out = (float*)d_out;

    cudaFuncSetAttribute(tc_step_kernel, cudaFuncAttributeMaxDynamicSharedMemorySize, FSMEM_TOT);

    init_state_kernel<<<(2 * BATCH * HID + 255) / 256, 256>>>();
    split_x_kernel<<<(int)(((size_t)SEQ * BATCH * EMB + 255) / 256), 256>>>(inputs, emb);
    prep_wx_kernel<<<dim3(EMB / 32, G4 / 32, 2), dim3(32, 8)>>>(Wx_f, Wx_b);
    prep_wh_kernel<<<dim3(HID / 32, G4 / 32, 2), dim3(32, 8)>>>(Wh_f, Wh_b);

    tc_pregemm_kernel<<<dim3(G4 / 128, SEQ * BATCH / 128, 2), 256>>>(b_f, b_b);

    for (int t = 0; t < SEQ; t++)
        tc_step_kernel<<<dim3(HID / 32, BATCH / 128, 2), 256, FSMEM_TOT>>>(t);

    head_kernel<<<BATCH, 256>>>(W_hq, b_q, out);
    (void)in_sizes; (void)n_in; (void)out_size;
}